// round 16
// baseline (speedup 1.0000x reference)
#include <cuda_runtime.h>

// Problem constants (fixed by setup_inputs)
#define BS   8
#define NA   128
#define NC   256
#define ZZ   8
#define NT   3
#define NET  9
#define NETASK (BS*NC*3)   // 6144 edge tasks
#define NNODE  (BS*NA)     // 1024 node tasks
#define NTASKS (NETASK + NNODE)  // 7168
#define OUT_LOGPI (BS*NC*ZZ*ZZ*ZZ)   // 1048576
#define NBIN 28            // producer (binning) CTAs
#define ECH 32             // chunks per edge type (capacity 1024)
#define NCH 16             // chunks per node type (capacity 512)
#define NCONS (NET*ECH + NT*NCH)   // 336 consumer CTAs
#define GRID_ALL (NBIN + NCONS)    // 364

typedef unsigned long long u64;

// ---------------- device scratch (no allocations allowed) ----------------
__device__ __align__(16) float g_nf[NNODE*ZZ];
__device__ __align__(16) float g_ef[NETASK*64];
__device__ int g_ecnt[NET];          // zero at load; re-zeroed by assemble
__device__ int g_ncnt[NT];
__device__ int g_ebucket[NET*NETASK];
__device__ int g_nbucket[NT*NNODE];
__device__ unsigned g_done;          // producer completion counter
__device__ unsigned g_flag[NCONS];   // per-consumer release flags

static __device__ __forceinline__ int clampi(int v, int lo, int hi) {
    return v < lo ? lo : (v > hi ? hi : v);
}

// ---------------- packed f32x2 helpers (FFMA2) ----------------
static __device__ __forceinline__ u64 pack2(float a, float b) {
    u64 r; asm("mov.b64 %0, {%1, %2};" : "=l"(r) : "f"(a), "f"(b)); return r;
}
static __device__ __forceinline__ void unpack2(u64 v, float& a, float& b) {
    asm("mov.b64 {%0, %1}, %2;" : "=f"(a), "=f"(b) : "l"(v));
}
static __device__ __forceinline__ void ffma2(u64& d, u64 a, u64 b) {
    asm("fma.rn.f32x2 %0, %1, %2, %0;" : "+l"(d) : "l"(a), "l"(b));
}

// ---------------- 32x64 @ 64x64 layer, 256 thr, 2 rows x 4 cols/thread ----
static __device__ __forceinline__ void layer64(const float* __restrict__ sIn,
                                               const float* __restrict__ sW,
                                               const float* __restrict__ sb,
                                               int r0, int colb, u64 acc[4]) {
    ulonglong2 bv = *(const ulonglong2*)(sb + colb);
    acc[0] = bv.x; acc[1] = bv.y; acc[2] = bv.x; acc[3] = bv.y;
    const float* in0 = sIn + r0*68;
    const float* in1 = sIn + (r0+4)*68;
    #pragma unroll
    for (int d0 = 0; d0 < 64; d0 += 4) {
        float4 x0 = *(const float4*)(in0 + d0);
        float4 x1 = *(const float4*)(in1 + d0);
        {
            ulonglong2 w = *(const ulonglong2*)(sW + (d0+0)*64 + colb);
            u64 a0 = pack2(x0.x, x0.x), a1 = pack2(x1.x, x1.x);
            ffma2(acc[0], a0, w.x); ffma2(acc[1], a0, w.y);
            ffma2(acc[2], a1, w.x); ffma2(acc[3], a1, w.y);
        }
        {
            ulonglong2 w = *(const ulonglong2*)(sW + (d0+1)*64 + colb);
            u64 a0 = pack2(x0.y, x0.y), a1 = pack2(x1.y, x1.y);
            ffma2(acc[0], a0, w.x); ffma2(acc[1], a0, w.y);
            ffma2(acc[2], a1, w.x); ffma2(acc[3], a1, w.y);
        }
        {
            ulonglong2 w = *(const ulonglong2*)(sW + (d0+2)*64 + colb);
            u64 a0 = pack2(x0.z, x0.z), a1 = pack2(x1.z, x1.z);
            ffma2(acc[0], a0, w.x); ffma2(acc[1], a0, w.y);
            ffma2(acc[2], a1, w.x); ffma2(acc[3], a1, w.y);
        }
        {
            ulonglong2 w = *(const ulonglong2*)(sW + (d0+3)*64 + colb);
            u64 a0 = pack2(x0.w, x0.w), a1 = pack2(x1.w, x1.w);
            ffma2(acc[0], a0, w.x); ffma2(acc[1], a0, w.y);
            ffma2(acc[2], a1, w.x); ffma2(acc[3], a1, w.y);
        }
    }
}

static __device__ __forceinline__ void store_relu(float* __restrict__ sOut,
                                                  int r0, int colb, const u64 acc[4]) {
    float a, b, c, d;
    unpack2(acc[0], a, b); unpack2(acc[1], c, d);
    *(float4*)(sOut + r0*68 + colb) =
        make_float4(fmaxf(a,0.f), fmaxf(b,0.f), fmaxf(c,0.f), fmaxf(d,0.f));
    unpack2(acc[2], a, b); unpack2(acc[3], c, d);
    *(float4*)(sOut + (r0+4)*68 + colb) =
        make_float4(fmaxf(a,0.f), fmaxf(b,0.f), fmaxf(c,0.f), fmaxf(d,0.f));
}

// ---------------- merged kernel: 28 producers + 336 static consumers -------
__global__ __launch_bounds__(256) void mlp_kernel(
    const int* __restrict__ types, const int* __restrict__ cni,
    const float* __restrict__ node_enc, const float* __restrict__ edge_enc,
    const float* __restrict__ nW0, const float* __restrict__ nb0,
    const float* __restrict__ nW1, const float* __restrict__ nb1,
    const float* __restrict__ nW2, const float* __restrict__ nb2,
    const float* __restrict__ eW0, const float* __restrict__ eb0,
    const float* __restrict__ eW1, const float* __restrict__ eb1,
    const float* __restrict__ eW2, const float* __restrict__ eb2)
{
    __shared__ __align__(16) float sW[64*64];
    __shared__ __align__(16) float sb0[64], sb1[64], sb2[64];
    __shared__ __align__(16) float sA[32*68];
    __shared__ __align__(16) float sB[32*68];
    __shared__ int s_idx[32];
    __shared__ int s_off[32];
    __shared__ int sLast;

    int tid = threadIdx.x;
    int bid = blockIdx.x;

    // ================= producers: bin 256 tasks, release, exit =============
    if (bid < NBIN) {
        int* h     = s_idx;
        int* basev = s_off;
        if (tid < 12) h[tid] = 0;
        __syncthreads();

        int t = bid * 256 + tid;
        int bk = -1, val = 0, pos = 0;
        if (t < NETASK) {
            int b   = t / (NC*3);
            int rem = t - b*(NC*3);
            int c   = rem / 3;
            int p   = rem - 3*c;          // pair: 0->(0,1) 1->(0,2) 2->(1,2)
            int a0  = (p == 2) ? 1 : 0;
            int a1  = (p == 0) ? 1 : 2;
            int i = clampi(cni[(b*NC + c)*3 + a0], 0, NA-1);
            int j = clampi(cni[(b*NC + c)*3 + a1], 0, NA-1);
            int ti = clampi(types[b*NA + i], 0, NT-1);
            int tj = clampi(types[b*NA + j], 0, NT-1);
            bk = tj*3 + ti;               // emask: pa==type[j], pb==type[i]
            val = t;
        } else if (t < NTASKS) {
            int nn = t - NETASK;
            bk = 9 + clampi(types[nn], 0, NT-1);
            val = nn;
        }
        if (bk >= 0) pos = atomicAdd(&h[bk], 1);
        __syncthreads();
        if (tid < 12 && h[tid] > 0) {
            basev[tid] = (tid < 9) ? atomicAdd(&g_ecnt[tid], h[tid])
                                   : atomicAdd(&g_ncnt[tid-9], h[tid]);
        }
        __syncthreads();
        if (bk >= 0) {
            int base = basev[bk];
            if (bk < 9) g_ebucket[bk*NETASK + base + pos] = val;
            else        g_nbucket[(bk-9)*NNODE + base + pos] = val;
        }
        __threadfence();                  // each thread's stores visible
        __syncthreads();
        if (tid == 0) {
            unsigned p = atomicAdd(&g_done, 1u);
            sLast = (p == NBIN - 1);
        }
        __syncthreads();
        if (sLast) {                      // last producer releases everyone
            __threadfence();
            for (int f = tid; f < NCONS; f += 256)
                atomicExch(&g_flag[f], 1u);   // distinct addrs: no hotspot
        }
        return;
    }

    // ================= consumers: static role, pre-wait staging ============
    int cid = bid - NBIN;
    bool isEdge = cid < NET*ECH;
    int g, base;
    if (isEdge) { g = cid >> 5; base = (cid & 31) * 32; }
    else { int nb = cid - NET*ECH; g = nb >> 4; base = (nb & 15) * 32; }

    const float *W0, *W1, *b0, *b1, *inBase;
    if (isEdge) {
        W0 = eW0 + g*4096; W1 = eW1 + g*4096;
        b0 = eb0 + g*64;   b1 = eb1 + g*64;
        inBase = edge_enc;
    } else {
        W0 = nW0 + g*4096; W1 = nW1 + g*4096;
        b0 = nb0 + g*64;   b1 = nb1 + g*64;
        inBase = node_enc;
    }

    // pre-wait: stage W0 + all biases (pure inputs, overlap producers)
    {
        const float4* w = (const float4*)W0;
        float4* sw = (float4*)sW;
        #pragma unroll
        for (int k = 0; k < 4; k++) sw[tid + 256*k] = w[tid + 256*k];
        if (tid < 64) {
            sb0[tid] = b0[tid];
            sb1[tid] = b1[tid];
            sb2[tid] = isEdge ? eb2[g*64 + tid] : (tid < 8 ? nb2[g*8 + tid] : 0.f);
        }
    }

    // wait on OWN flag (per-consumer address: no poll hotspot)
    if (tid == 0) {
        while (__ldcg(&g_flag[cid]) == 0u) __nanosleep(64);
        __threadfence();                  // acquire
    }
    __syncthreads();

    int cnt = isEdge ? __ldcg(&g_ecnt[g]) : __ldcg(&g_ncnt[g]);
    if (base >= cnt) return;              // empty chunk: cheap uniform exit
    int ntask = min(32, cnt - base);

    int warp = tid >> 5, lane = tid & 31;
    int colb = (warp & 1) * 32 + (lane & 7) * 4;
    int r0   = (warp >> 1) * 8 + (lane >> 3);

    if (tid < ntask) {
        if (isEdge) {
            int tt = __ldcg(&g_ebucket[g*NETASK + base + tid]);
            s_idx[tid] = tt;
            int b   = tt / (NC*3);
            int rem = tt - b*(NC*3);
            int c   = rem / 3;
            int p   = rem - 3*c;
            int a0  = (p == 2) ? 1 : 0;
            int a1  = (p == 0) ? 1 : 2;
            int i = clampi(cni[(b*NC + c)*3 + a0], 0, NA-1);
            int j = clampi(cni[(b*NC + c)*3 + a1], 0, NA-1);
            s_off[tid] = ((b*NA + i)*NA + j) * 64;
        } else {
            int nn = __ldcg(&g_nbucket[g*NNODE + base + tid]);
            s_idx[tid] = nn;
            s_off[tid] = nn * 64;
        }
    }
    __syncthreads();

    // gather inputs, prefetch W1 into regs
    float4 pw[4];
    {
        const float4* w = (const float4*)W1;
        #pragma unroll
        for (int k = 0; k < 4; k++) pw[k] = w[tid + 256*k];
    }
    for (int k = tid; k < ntask*16; k += 256) {
        int s = k >> 4, q = k & 15;
        float4 v = *(const float4*)(inBase + (size_t)s_off[s] + q*4);
        *(float4*)(sA + s*68 + q*4) = v;
    }
    __syncthreads();

    u64 a4[4];
    layer64(sA, sW, sb0, r0, colb, a4);          // layer 0
    __syncthreads();
    store_relu(sB, r0, colb, a4);
    {
        float4* sw = (float4*)sW;
        #pragma unroll
        for (int k = 0; k < 4; k++) sw[tid + 256*k] = pw[k];
    }
    if (isEdge) {
        const float4* w = (const float4*)(eW2 + g*4096);
        #pragma unroll
        for (int k = 0; k < 4; k++) pw[k] = w[tid + 256*k];
    } else {
        if (tid < 128) pw[0] = ((const float4*)(nW2 + g*512))[tid];
    }
    __syncthreads();

    layer64(sB, sW, sb1, r0, colb, a4);          // layer 1
    __syncthreads();
    store_relu(sA, r0, colb, a4);
    {
        float4* sw = (float4*)sW;
        if (isEdge) {
            #pragma unroll
            for (int k = 0; k < 4; k++) sw[tid + 256*k] = pw[k];
        } else {
            if (tid < 128) sw[tid] = pw[0];
        }
    }
    __syncthreads();

    if (isEdge) {                                 // layer 2 (edge)
        layer64(sA, sW, sb2, r0, colb, a4);
        float a, b, c, d;
        if (r0 < ntask) {
            unpack2(a4[0], a, b); unpack2(a4[1], c, d);
            *(float4*)(g_ef + (size_t)s_idx[r0]*64 + colb) = make_float4(a, b, c, d);
        }
        if (r0 + 4 < ntask) {
            unpack2(a4[2], a, b); unpack2(a4[3], c, d);
            *(float4*)(g_ef + (size_t)s_idx[r0+4]*64 + colb) = make_float4(a, b, c, d);
        }
    } else {                                      // layer 2 (node, 64->8)
        int row = tid >> 3, col = tid & 7;
        float a = sb2[col];
        const float* in = sA + row*68;
        #pragma unroll 16
        for (int d = 0; d < 64; d++) a += in[d] * sW[d*8 + col];
        if (row < ntask) g_nf[(size_t)s_idx[row]*8 + col] = a;
    }
    __threadfence();
    cudaTriggerProgrammaticLaunchCompletion();
}

// ---------------- assemble: warp-per-clique, PDL, resets scratch -----------
__global__ __launch_bounds__(256) void assemble_kernel(
    const int* __restrict__ cni, float* __restrict__ out, int writeZ)
{
    __shared__ float sE[8][192 + 8];
    __shared__ float sN[8][24 + 8];

    int tid  = threadIdx.x;
    int warp = tid >> 5, lane = tid & 31;
    int cq   = blockIdx.x * 8 + warp;

    // PRE-SYNC: z tail (out region untouched by mlp)
    if (blockIdx.x == 0 && writeZ) {
        for (int m = tid; m < 512; m += 256) {
            int i = m >> 6, j = (m >> 3) & 7, k = m & 7;
            float* p = out + OUT_LOGPI + (size_t)m*3;
            p[0] = (float)i; p[1] = (float)j; p[2] = (float)k;
        }
    }
    // PRE-SYNC: node indices (cni is a pure input)
    int node_k = 0;
    if (lane < 24) node_k = clampi(cni[cq*3 + (lane >> 3)], 0, NA-1);

    cudaGridDependencySynchronize();

    // post-sync: reset scratch for next replay (mlp grid fully done)
    if (blockIdx.x == 0) {
        if (tid < NET) g_ecnt[tid] = 0;
        if (tid < NT)  g_ncnt[tid] = 0;
        if (tid == 0)  g_done = 0;
    }
    if (blockIdx.x == 1) {
        for (int f = tid; f < NCONS; f += 256) g_flag[f] = 0u;
    }

    size_t tbase = (size_t)cq * 192;
    #pragma unroll
    for (int k = 0; k < 6; k++)
        sE[warp][lane + 32*k] = __ldcg(&g_ef[tbase + lane + 32*k]);
    if (lane < 24) {
        int k = lane >> 3, zz = lane & 7;
        int b = cq >> 8;
        sN[warp][k*8 + zz] = __ldcg(&g_nf[((size_t)b*NA + node_k)*8 + zz]);
    }
    __syncwarp();

    const float* e = sE[warp];
    const float* nf = sN[warp];
    #pragma unroll
    for (int half = 0; half < 2; half++) {
        int p  = lane + half*32;
        int z0 = p >> 3, z1 = p & 7;
        float bse = nf[z0] + nf[8 + z1] + e[p];
        float r[8];
        #pragma unroll
        for (int z2 = 0; z2 < 8; z2++)
            r[z2] = bse + nf[16 + z2] + e[64 + z0*8 + z2] + e[128 + z1*8 + z2];
        float* op = out + (size_t)cq*512 + p*8;
        *(float4*)op       = make_float4(r[0], r[1], r[2], r[3]);
        *(float4*)(op + 4) = make_float4(r[4], r[5], r[6], r[7]);
    }
}

// ---------------- launch ----------------
extern "C" void kernel_launch(void* const* d_in, const int* in_sizes, int n_in,
                              void* d_out, int out_size) {
    const int*   types    = (const int*)d_in[0];
    const float* node_enc = (const float*)d_in[1];
    const float* edge_enc = (const float*)d_in[2];
    const int*   cni      = (const int*)d_in[4];
    const float* nW0 = (const float*)d_in[6];
    const float* nb0 = (const float*)d_in[7];
    const float* nW1 = (const float*)d_in[8];
    const float* nb1 = (const float*)d_in[9];
    const float* nW2 = (const float*)d_in[10];
    const float* nb2 = (const float*)d_in[11];
    const float* eW0 = (const float*)d_in[12];
    const float* eb0 = (const float*)d_in[13];
    const float* eW1 = (const float*)d_in[14];
    const float* eb1 = (const float*)d_in[15];
    const float* eW2 = (const float*)d_in[16];
    const float* eb2 = (const float*)d_in[17];
    float* out = (float*)d_out;

    int writeZ = (out_size >= OUT_LOGPI + 512*3) ? 1 : 0;

    // merged producer+consumer kernel (364 CTAs, all co-resident)
    mlp_kernel<<<GRID_ALL, 256>>>(types, cni, node_enc, edge_enc,
                                  nW0, nb0, nW1, nb1, nW2, nb2,
                                  eW0, eb0, eW1, eb1, eW2, eb2);

    // PDL on mlp->assemble (pre-sync work is tiny: z-tail + cni loads)
    cudaLaunchAttribute attr[1];
    attr[0].id = cudaLaunchAttributeProgrammaticStreamSerialization;
    attr[0].val.programmaticStreamSerializationAllowed = 1;
    cudaLaunchConfig_t cfg = {};
    cfg.gridDim  = dim3(BS * NC / 8, 1, 1);
    cfg.blockDim = dim3(256, 1, 1);
    cfg.stream   = 0;
    cfg.attrs    = attr;
    cfg.numAttrs = 1;
    cudaLaunchKernelEx(&cfg, assemble_kernel, cni, out, writeZ);
}

// round 17
// speedup vs baseline: 1.0890x; 1.0890x over previous
#include <cuda_runtime.h>

// Problem constants (fixed by setup_inputs)
#define BS   8
#define NA   128
#define NC   256
#define ZZ   8
#define NT   3
#define NET  9
#define NETASK (BS*NC*3)   // 6144 edge tasks
#define NNODE  (BS*NA)     // 1024 nodes
#define OUT_LOGPI (BS*NC*ZZ*ZZ*ZZ)   // 1048576
#define NBIN 24            // edge binning CTAs (6144/256)
#define NNMLP 96           // node MLP CTAs (3 types x 32 chunks)
#define EGRID 201          // edge MLP grid (<= 192+9 chunks)

typedef unsigned long long u64;

// ---------------- device scratch (no allocations allowed) ----------------
__device__ __align__(16) float g_nf[NNODE*ZZ];
__device__ __align__(16) float g_ef[NETASK*64];
__device__ int g_ecnt[NET];          // zero at load; re-zeroed by assemble
__device__ int g_ebucket[NET*NETASK];

static __device__ __forceinline__ int clampi(int v, int lo, int hi) {
    return v < lo ? lo : (v > hi ? hi : v);
}

// ---------------- packed f32x2 helpers (FFMA2) ----------------
static __device__ __forceinline__ u64 pack2(float a, float b) {
    u64 r; asm("mov.b64 %0, {%1, %2};" : "=l"(r) : "f"(a), "f"(b)); return r;
}
static __device__ __forceinline__ void unpack2(u64 v, float& a, float& b) {
    asm("mov.b64 {%0, %1}, %2;" : "=f"(a), "=f"(b) : "l"(v));
}
static __device__ __forceinline__ void ffma2(u64& d, u64 a, u64 b) {
    asm("fma.rn.f32x2 %0, %1, %2, %0;" : "+l"(d) : "l"(a), "l"(b));
}

// ---------------- 32x64 @ 64x64 layer, 256 thr, 2 rows x 4 cols/thread ----
static __device__ __forceinline__ void layer64(const float* __restrict__ sIn,
                                               const float* __restrict__ sW,
                                               const float* __restrict__ sb,
                                               int r0, int colb, u64 acc[4]) {
    ulonglong2 bv = *(const ulonglong2*)(sb + colb);
    acc[0] = bv.x; acc[1] = bv.y; acc[2] = bv.x; acc[3] = bv.y;
    const float* in0 = sIn + r0*68;
    const float* in1 = sIn + (r0+4)*68;
    #pragma unroll
    for (int d0 = 0; d0 < 64; d0 += 4) {
        float4 x0 = *(const float4*)(in0 + d0);
        float4 x1 = *(const float4*)(in1 + d0);
        {
            ulonglong2 w = *(const ulonglong2*)(sW + (d0+0)*64 + colb);
            u64 a0 = pack2(x0.x, x0.x), a1 = pack2(x1.x, x1.x);
            ffma2(acc[0], a0, w.x); ffma2(acc[1], a0, w.y);
            ffma2(acc[2], a1, w.x); ffma2(acc[3], a1, w.y);
        }
        {
            ulonglong2 w = *(const ulonglong2*)(sW + (d0+1)*64 + colb);
            u64 a0 = pack2(x0.y, x0.y), a1 = pack2(x1.y, x1.y);
            ffma2(acc[0], a0, w.x); ffma2(acc[1], a0, w.y);
            ffma2(acc[2], a1, w.x); ffma2(acc[3], a1, w.y);
        }
        {
            ulonglong2 w = *(const ulonglong2*)(sW + (d0+2)*64 + colb);
            u64 a0 = pack2(x0.z, x0.z), a1 = pack2(x1.z, x1.z);
            ffma2(acc[0], a0, w.x); ffma2(acc[1], a0, w.y);
            ffma2(acc[2], a1, w.x); ffma2(acc[3], a1, w.y);
        }
        {
            ulonglong2 w = *(const ulonglong2*)(sW + (d0+3)*64 + colb);
            u64 a0 = pack2(x0.w, x0.w), a1 = pack2(x1.w, x1.w);
            ffma2(acc[0], a0, w.x); ffma2(acc[1], a0, w.y);
            ffma2(acc[2], a1, w.x); ffma2(acc[3], a1, w.y);
        }
    }
}

static __device__ __forceinline__ void store_relu(float* __restrict__ sOut,
                                                  int r0, int colb, const u64 acc[4]) {
    float a, b, c, d;
    unpack2(acc[0], a, b); unpack2(acc[1], c, d);
    *(float4*)(sOut + r0*68 + colb) =
        make_float4(fmaxf(a,0.f), fmaxf(b,0.f), fmaxf(c,0.f), fmaxf(d,0.f));
    unpack2(acc[2], a, b); unpack2(acc[3], c, d);
    *(float4*)(sOut + (r0+4)*68 + colb) =
        make_float4(fmaxf(a,0.f), fmaxf(b,0.f), fmaxf(c,0.f), fmaxf(d,0.f));
}

// ======= K1: 24 edge-bin CTAs + 96 masked node-MLP CTAs (independent) ======
__global__ __launch_bounds__(256) void bin_node_kernel(
    const int* __restrict__ types, const int* __restrict__ cni,
    const float* __restrict__ node_enc,
    const float* __restrict__ nW0, const float* __restrict__ nb0,
    const float* __restrict__ nW1, const float* __restrict__ nb1,
    const float* __restrict__ nW2, const float* __restrict__ nb2)
{
    __shared__ __align__(16) float sW[64*64];
    __shared__ __align__(16) float sb0[64], sb1[64], sb2[64];
    __shared__ __align__(16) float sA[32*68];
    __shared__ __align__(16) float sB[32*68];
    __shared__ int s_h[12];
    __shared__ int s_b[12];

    int tid = threadIdx.x;
    int bid = blockIdx.x;

    // ---------------- edge binning (exact champion code, edges only) -------
    if (bid < NBIN) {
        if (tid < NET) s_h[tid] = 0;
        __syncthreads();

        int t = bid * 256 + tid;          // t < 6144 always
        int b   = t / (NC*3);
        int rem = t - b*(NC*3);
        int c   = rem / 3;
        int p   = rem - 3*c;              // pair: 0->(0,1) 1->(0,2) 2->(1,2)
        int a0  = (p == 2) ? 1 : 0;
        int a1  = (p == 0) ? 1 : 2;
        int i = clampi(cni[(b*NC + c)*3 + a0], 0, NA-1);
        int j = clampi(cni[(b*NC + c)*3 + a1], 0, NA-1);
        int ti = clampi(types[b*NA + i], 0, NT-1);
        int tj = clampi(types[b*NA + j], 0, NT-1);
        int bk = tj*3 + ti;               // emask: pa==type[j], pb==type[i]
        int pos = atomicAdd(&s_h[bk], 1);
        __syncthreads();
        if (tid < NET && s_h[tid] > 0)
            s_b[tid] = atomicAdd(&g_ecnt[tid], s_h[tid]);
        __syncthreads();
        g_ebucket[bk*NETASK + s_b[bk] + pos] = t;
        return;
    }

    // ---------------- node MLP, unbinned, type-masked writes ---------------
    {
        int cid = bid - NBIN;             // 0..95
        int g    = cid >> 5;              // type 0..2
        int nb0i = (cid & 31) * 32;       // first node of this chunk

        // stage W0 + biases
        {
            const float4* w = (const float4*)(nW0 + g*4096);
            float4* sw = (float4*)sW;
            #pragma unroll
            for (int k = 0; k < 4; k++) sw[tid + 256*k] = w[tid + 256*k];
            if (tid < 64) { sb0[tid] = nb0[g*64 + tid]; sb1[tid] = nb1[g*64 + tid]; }
            if (tid < 8)  sb2[tid] = nb2[g*8 + tid];
        }
        __syncthreads();

        // gather 32 consecutive node rows (fully coalesced), prefetch W1
        float4 pw[4];
        {
            const float4* w = (const float4*)(nW1 + g*4096);
            #pragma unroll
            for (int k = 0; k < 4; k++) pw[k] = w[tid + 256*k];
        }
        {
            int s = tid >> 4, q = tid & 15;
            const float* src = node_enc + (size_t)(nb0i)*64;
            *(float4*)(sA + s*68 + q*4)      = *(const float4*)(src + (size_t)s*64      + q*4);
            *(float4*)(sA + (s+16)*68 + q*4) = *(const float4*)(src + (size_t)(s+16)*64 + q*4);
        }
        __syncthreads();

        int warp = tid >> 5, lane = tid & 31;
        int colb = (warp & 1) * 32 + (lane & 7) * 4;
        int r0   = (warp >> 1) * 8 + (lane >> 3);

        u64 a4[4];
        layer64(sA, sW, sb0, r0, colb, a4);          // layer 0
        __syncthreads();
        store_relu(sB, r0, colb, a4);
        {
            float4* sw = (float4*)sW;
            #pragma unroll
            for (int k = 0; k < 4; k++) sw[tid + 256*k] = pw[k];
        }
        if (tid < 128) pw[0] = ((const float4*)(nW2 + g*512))[tid];
        __syncthreads();

        layer64(sB, sW, sb1, r0, colb, a4);          // layer 1
        __syncthreads();
        store_relu(sA, r0, colb, a4);
        if (tid < 128) ((float4*)sW)[tid] = pw[0];   // W2 (64x8)
        __syncthreads();

        // layer 2: 64 -> 8, one output per thread; masked write
        int row = tid >> 3, col = tid & 7;
        int nn  = nb0i + row;
        float a = sb2[col];
        const float* in = sA + row*68;
        #pragma unroll 16
        for (int d = 0; d < 64; d++) a += in[d] * sW[d*8 + col];
        if (clampi(types[nn], 0, NT-1) == g)
            g_nf[(size_t)nn*8 + col] = a;
    }
}

// ======= K2: edge MLP, prefix-scan role map over 9 edge types ==============
__global__ __launch_bounds__(256) void edge_mlp_kernel(
    const float* __restrict__ edge_enc, const int* __restrict__ cni,
    const float* __restrict__ eW0, const float* __restrict__ eb0,
    const float* __restrict__ eW1, const float* __restrict__ eb1,
    const float* __restrict__ eW2, const float* __restrict__ eb2)
{
    int bid = blockIdx.x;
    int g = -1, chunk = 0, acc = 0, cnt = 0;
    #pragma unroll
    for (int t = 0; t < NET; t++) {
        int n = g_ecnt[t];
        int c = (n + 31) >> 5;
        if (g < 0 && bid < acc + c) { g = t; chunk = bid - acc; cnt = n; }
        acc += c;
    }
    if (g < 0) return;
    int base  = chunk * 32;
    int ntask = min(32, cnt - base);

    __shared__ __align__(16) float sW[64*64];
    __shared__ __align__(16) float sb0[64], sb1[64], sb2[64];
    __shared__ __align__(16) float sA[32*68];
    __shared__ __align__(16) float sB[32*68];
    __shared__ int s_idx[32];
    __shared__ int s_off[32];

    int tid  = threadIdx.x;
    int warp = tid >> 5, lane = tid & 31;
    int colb = (warp & 1) * 32 + (lane & 7) * 4;
    int r0   = (warp >> 1) * 8 + (lane >> 3);

    if (tid < ntask) {
        int tt = g_ebucket[g*NETASK + base + tid];
        s_idx[tid] = tt;
        int b   = tt / (NC*3);
        int rem = tt - b*(NC*3);
        int c   = rem / 3;
        int p   = rem - 3*c;
        int a0  = (p == 2) ? 1 : 0;
        int a1  = (p == 0) ? 1 : 2;
        int i = clampi(cni[(b*NC + c)*3 + a0], 0, NA-1);
        int j = clampi(cni[(b*NC + c)*3 + a1], 0, NA-1);
        s_off[tid] = ((b*NA + i)*NA + j) * 64;
    }

    {
        const float4* w = (const float4*)(eW0 + g*4096);
        float4* sw = (float4*)sW;
        #pragma unroll
        for (int k = 0; k < 4; k++) sw[tid + 256*k] = w[tid + 256*k];
        if (tid < 64) { sb0[tid] = eb0[g*64 + tid]; sb1[tid] = eb1[g*64 + tid]; }
    }
    __syncthreads();

    float4 pw[4];
    {
        const float4* w = (const float4*)(eW1 + g*4096);
        #pragma unroll
        for (int k = 0; k < 4; k++) pw[k] = w[tid + 256*k];
    }
    for (int k = tid; k < ntask*16; k += 256) {
        int s = k >> 4, q = k & 15;
        float4 v = *(const float4*)(edge_enc + (size_t)s_off[s] + q*4);
        *(float4*)(sA + s*68 + q*4) = v;
    }
    __syncthreads();

    u64 a4[4];
    layer64(sA, sW, sb0, r0, colb, a4);          // layer 0
    __syncthreads();
    store_relu(sB, r0, colb, a4);
    {
        float4* sw = (float4*)sW;
        #pragma unroll
        for (int k = 0; k < 4; k++) sw[tid + 256*k] = pw[k];
    }
    {
        const float4* w = (const float4*)(eW2 + g*4096);
        #pragma unroll
        for (int k = 0; k < 4; k++) pw[k] = w[tid + 256*k];
        if (tid < 64) sb2[tid] = eb2[g*64 + tid];
    }
    __syncthreads();

    layer64(sB, sW, sb1, r0, colb, a4);          // layer 1
    __syncthreads();
    store_relu(sA, r0, colb, a4);
    {
        float4* sw = (float4*)sW;
        #pragma unroll
        for (int k = 0; k < 4; k++) sw[tid + 256*k] = pw[k];
    }
    __syncthreads();

    layer64(sA, sW, sb2, r0, colb, a4);          // layer 2 (no relu)
    float a, b, c, d;
    if (r0 < ntask) {
        unpack2(a4[0], a, b); unpack2(a4[1], c, d);
        *(float4*)(g_ef + (size_t)s_idx[r0]*64 + colb) = make_float4(a, b, c, d);
    }
    if (r0 + 4 < ntask) {
        unpack2(a4[2], a, b); unpack2(a4[3], c, d);
        *(float4*)(g_ef + (size_t)s_idx[r0+4]*64 + colb) = make_float4(a, b, c, d);
    }
    __threadfence();
    cudaTriggerProgrammaticLaunchCompletion();
}

// ======= K3: assemble, warp-per-clique, PDL, resets g_ecnt ==================
__global__ __launch_bounds__(256) void assemble_kernel(
    const int* __restrict__ cni, float* __restrict__ out, int writeZ)
{
    __shared__ float sE[8][192 + 8];
    __shared__ float sN[8][24 + 8];

    int tid  = threadIdx.x;
    int warp = tid >> 5, lane = tid & 31;
    int cq   = blockIdx.x * 8 + warp;

    // PRE-SYNC: z tail (out region untouched by mlp)
    if (blockIdx.x == 0 && writeZ) {
        for (int m = tid; m < 512; m += 256) {
            int i = m >> 6, j = (m >> 3) & 7, k = m & 7;
            float* p = out + OUT_LOGPI + (size_t)m*3;
            p[0] = (float)i; p[1] = (float)j; p[2] = (float)k;
        }
    }
    // PRE-SYNC: node indices (cni is a pure input)
    int node_k = 0;
    if (lane < 24) node_k = clampi(cni[cq*3 + (lane >> 3)], 0, NA-1);

    cudaGridDependencySynchronize();

    if (blockIdx.x == 0 && tid < NET) g_ecnt[tid] = 0;   // reset for replay

    size_t tbase = (size_t)cq * 192;
    #pragma unroll
    for (int k = 0; k < 6; k++)
        sE[warp][lane + 32*k] = __ldcg(&g_ef[tbase + lane + 32*k]);
    if (lane < 24) {
        int k = lane >> 3, zz = lane & 7;
        int b = cq >> 8;
        sN[warp][k*8 + zz] = __ldcg(&g_nf[((size_t)b*NA + node_k)*8 + zz]);
    }
    __syncwarp();

    const float* e = sE[warp];
    const float* nf = sN[warp];
    #pragma unroll
    for (int half = 0; half < 2; half++) {
        int p  = lane + half*32;
        int z0 = p >> 3, z1 = p & 7;
        float bse = nf[z0] + nf[8 + z1] + e[p];
        float r[8];
        #pragma unroll
        for (int z2 = 0; z2 < 8; z2++)
            r[z2] = bse + nf[16 + z2] + e[64 + z0*8 + z2] + e[128 + z1*8 + z2];
        float* op = out + (size_t)cq*512 + p*8;
        *(float4*)op       = make_float4(r[0], r[1], r[2], r[3]);
        *(float4*)(op + 4) = make_float4(r[4], r[5], r[6], r[7]);
    }
}

// ---------------- launch ----------------
extern "C" void kernel_launch(void* const* d_in, const int* in_sizes, int n_in,
                              void* d_out, int out_size) {
    const int*   types    = (const int*)d_in[0];
    const float* node_enc = (const float*)d_in[1];
    const float* edge_enc = (const float*)d_in[2];
    const int*   cni      = (const int*)d_in[4];
    const float* nW0 = (const float*)d_in[6];
    const float* nb0 = (const float*)d_in[7];
    const float* nW1 = (const float*)d_in[8];
    const float* nb1 = (const float*)d_in[9];
    const float* nW2 = (const float*)d_in[10];
    const float* nb2 = (const float*)d_in[11];
    const float* eW0 = (const float*)d_in[12];
    const float* eb0 = (const float*)d_in[13];
    const float* eW1 = (const float*)d_in[14];
    const float* eb1 = (const float*)d_in[15];
    const float* eW2 = (const float*)d_in[16];
    const float* eb2 = (const float*)d_in[17];
    float* out = (float*)d_out;

    int writeZ = (out_size >= OUT_LOGPI + 512*3) ? 1 : 0;

    // K1: edge binning (24 CTAs) + unbinned node MLP (96 CTAs), independent
    bin_node_kernel<<<NBIN + NNMLP, 256>>>(types, cni, node_enc,
                                           nW0, nb0, nW1, nb1, nW2, nb2);
    // K2: edge MLP (plain launch; bin->mlp overlap measured harmful)
    edge_mlp_kernel<<<EGRID, 256>>>(edge_enc, cni,
                                    eW0, eb0, eW1, eb1, eW2, eb2);
    // K3: assemble under PDL (pre-sync work tiny)
    cudaLaunchAttribute attr[1];
    attr[0].id = cudaLaunchAttributeProgrammaticStreamSerialization;
    attr[0].val.programmaticStreamSerializationAllowed = 1;
    cudaLaunchConfig_t cfg = {};
    cfg.gridDim  = dim3(BS * NC / 8, 1, 1);
    cfg.blockDim = dim3(256, 1, 1);
    cfg.stream   = 0;
    cfg.attrs    = attr;
    cfg.numAttrs = 1;
    cudaLaunchKernelEx(&cfg, assemble_kernel, cni, out, writeZ);
}